// round 2
// baseline (speedup 1.0000x reference)
#include <cuda_runtime.h>
#include <math.h>
#include <stdint.h>

// ---------------------------------------------------------------------------
// KNRM fused kernel (Round 1: SIMT fp32 baseline)
//   per CTA: one (pair, batch): gather+norm Q/D embeddings, 32x256 cosine GEMM
//   (fp32, K-chunked smem), 21 Gaussian soft-bins, log1p-sum, 3-layer MLP.
//   Kernel 2: sigmoid(l1 - l2).
// ---------------------------------------------------------------------------

#define THREADS   256
#define QLEN      32
#define DLEN      256
#define EMB_D     256
#define KCHUNK    64
#define NKC       (EMB_D / KCHUNK)      // 4
#define QT_PITCH  36                     // 256+pad? actually QL+pad: 32 -> 36 (144B, 16B-aligned rows)
#define DT_PITCH  260                    // 256+4  (1040B rows, 16B-aligned)
#define KNUM      21
#define BATCH     512

// -50/sigma^2 * log2(e) constants for exp2-based Gaussian
#define K2L  (-72.13475204444817f)       // sigma = 0.1   : -0.5/0.01  * log2(e)
#define K2E  (-721347.5204444817f)       // sigma = 0.001 : -0.5/1e-6  * log2(e)

struct SmemLayout {
    float qT[EMB_D][QT_PITCH];   // transposed raw query embeddings [k][q]
    float dT[KCHUNK][DT_PITCH];  // transposed raw doc chunk        [k][d]
    float qscale[QLEN];
    float dscale[DLEN];
    float qpart[8][QLEN];        // per-warp partial sumsq for q rows
    float ksum[QLEN][KNUM];
    float km[KNUM];
};

__device__ float g_logits[2][BATCH];

__device__ __forceinline__ float fast_ex2(float x) {
    float y;
    asm("ex2.approx.ftz.f32 %0, %1;" : "=f"(y) : "f"(x));
    return y;
}

__global__ void __launch_bounds__(THREADS)
knrm_main(const int* __restrict__ q1, const int* __restrict__ d1,
          const int* __restrict__ q2, const int* __restrict__ d2,
          const float* __restrict__ emb,
          const float* __restrict__ W0, const float* __restrict__ b0,
          const float* __restrict__ W1, const float* __restrict__ b1,
          const float* __restrict__ W2, const float* __restrict__ b2)
{
    extern __shared__ unsigned char smem_raw[];
    SmemLayout& S = *reinterpret_cast<SmemLayout*>(smem_raw);

    const int b    = blockIdx.x;
    const int pair = blockIdx.y;
    const int* qtok_g = (pair == 0 ? q1 : q2) + b * QLEN;
    const int* dtok_g = (pair == 0 ? d1 : d2) + b * DLEN;

    const int t = threadIdx.x;
    const int w = t >> 5;     // warp id 0..7
    const int L = t & 31;     // lane

    // ---- Load Q embeddings: warp w loads cols [32w,32w+32) of all 32 rows,
    //      lane <-> row. Transposed STS is conflict-free (bank=(4k+L)%32).
    {
        const int   tok = qtok_g[L];
        const float* row = emb + (size_t)tok * EMB_D + w * 32;
        float ss = 0.f;
        #pragma unroll
        for (int i = 0; i < 8; i++) {
            float4 v = *(const float4*)(row + 4 * i);
            int k = w * 32 + 4 * i;
            S.qT[k + 0][L] = v.x;
            S.qT[k + 1][L] = v.y;
            S.qT[k + 2][L] = v.z;
            S.qT[k + 3][L] = v.w;
            ss = fmaf(v.x, v.x, ss);
            ss = fmaf(v.y, v.y, ss);
            ss = fmaf(v.z, v.z, ss);
            ss = fmaf(v.w, v.w, ss);
        }
        S.qpart[w][L] = ss;
    }
    __syncthreads();

    // ---- Q norms (warp 0, deterministic fixed-order 8-term sum)
    if (w == 0) {
        float ss = 0.f;
        #pragma unroll
        for (int i = 0; i < 8; i++) ss += S.qpart[i][L];
        S.qscale[L] = 1.0f / fmaxf(sqrtf(ss), 1e-8f);
    }

    // ---- Main loop: C[32x256] accumulated in registers (4q x 8d per thread),
    //      doc embeddings streamed through smem in 4 K-chunks of 64.
    const int q0 = w * 4;                 // this warp's 4 query rows
    const int drow_id = w * 32 + L;       // this thread's gather row (0..255)
    const int dtok = dtok_g[drow_id];
    const float* drow = emb + (size_t)dtok * EMB_D;

    float C[4][8];
    #pragma unroll
    for (int qi = 0; qi < 4; qi++)
        #pragma unroll
        for (int j = 0; j < 8; j++) C[qi][j] = 0.f;

    float dss = 0.f;

    for (int kc = 0; kc < NKC; kc++) {
        __syncthreads();   // previous chunk fully consumed
        // gather + transpose-store this K-chunk of this thread's doc row
        #pragma unroll 4
        for (int i = 0; i < 16; i++) {
            float4 v = *(const float4*)(drow + kc * KCHUNK + 4 * i);
            int kk = 4 * i;
            S.dT[kk + 0][drow_id] = v.x;
            S.dT[kk + 1][drow_id] = v.y;
            S.dT[kk + 2][drow_id] = v.z;
            S.dT[kk + 3][drow_id] = v.w;
            dss = fmaf(v.x, v.x, dss);
            dss = fmaf(v.y, v.y, dss);
            dss = fmaf(v.z, v.z, dss);
            dss = fmaf(v.w, v.w, dss);
        }
        __syncthreads();   // chunk ready

        // GEMM over this K-chunk: per k: 1 bcast LDS.128 (q) + 2 LDS.128 (d)
        // + 32 FFMA  -> FMA-bound
        #pragma unroll 4
        for (int kk = 0; kk < KCHUNK; kk++) {
            float4 qf = *(const float4*)(&S.qT[kc * KCHUNK + kk][q0]);
            float4 da = *(const float4*)(&S.dT[kk][4 * L]);
            float4 db = *(const float4*)(&S.dT[kk][128 + 4 * L]);
            float qv[4] = {qf.x, qf.y, qf.z, qf.w};
            float dv[8] = {da.x, da.y, da.z, da.w, db.x, db.y, db.z, db.w};
            #pragma unroll
            for (int qi = 0; qi < 4; qi++)
                #pragma unroll
                for (int j = 0; j < 8; j++)
                    C[qi][j] = fmaf(qv[qi], dv[j], C[qi][j]);
        }
    }

    __syncthreads();
    S.dscale[drow_id] = 1.0f / fmaxf(sqrtf(dss), 1e-8f);
    __syncthreads();

    // ---- Gaussian soft-binning. Thread's docs: {4L..4L+3} and {128+4L..}
    {
        float qs[4];
        #pragma unroll
        for (int qi = 0; qi < 4; qi++) qs[qi] = S.qscale[q0 + qi];
        float4 dsa = *(const float4*)(&S.dscale[4 * L]);
        float4 dsb = *(const float4*)(&S.dscale[128 + 4 * L]);
        float dsv[8] = {dsa.x, dsa.y, dsa.z, dsa.w, dsb.x, dsb.y, dsb.z, dsb.w};

        #pragma unroll
        for (int qi = 0; qi < 4; qi++) {
            float kacc[KNUM];
            #pragma unroll
            for (int k = 0; k < KNUM; k++) kacc[k] = 0.f;

            #pragma unroll
            for (int j = 0; j < 8; j++) {
                float x = C[qi][j] * (qs[qi] * dsv[j]);   // cosine sim
                #pragma unroll
                for (int k = 0; k < 20; k++) {
                    float d0 = x - (-0.95f + 0.1f * (float)k);
                    kacc[k] += fast_ex2(d0 * d0 * K2L);
                }
                float de = x - 1.0f;                      // exact-match kernel
                kacc[20] += fast_ex2(de * de * K2E);
            }

            // warp-reduce over 32 lanes (all lanes share q rows q0..q0+3)
            #pragma unroll
            for (int k = 0; k < KNUM; k++) {
                float v = kacc[k];
                v += __shfl_xor_sync(0xffffffffu, v, 16);
                v += __shfl_xor_sync(0xffffffffu, v, 8);
                v += __shfl_xor_sync(0xffffffffu, v, 4);
                v += __shfl_xor_sync(0xffffffffu, v, 2);
                v += __shfl_xor_sync(0xffffffffu, v, 1);
                if (L == 0) S.ksum[q0 + qi][k] = v;   // single writer, no atomics
            }
        }
    }
    __syncthreads();

    // ---- km[k] = sum_q log1p(ksum[q][k])
    if (w == 0 && L < KNUM) {
        float s = 0.f;
        #pragma unroll 4
        for (int q = 0; q < QLEN; q++) s += log1pf(S.ksum[q][L]);
        S.km[L] = s;
    }
    __syncthreads();

    // ---- tiny MLP (thread 0)
    if (t == 0) {
        float h0[10];
        #pragma unroll
        for (int o = 0; o < 10; o++) {
            float acc = b0[o];
            #pragma unroll
            for (int k = 0; k < KNUM; k++) acc = fmaf(S.km[k], W0[o * KNUM + k], acc);
            h0[o] = fmaxf(acc, 0.f);
        }
        float h1[5];
        #pragma unroll
        for (int o = 0; o < 5; o++) {
            float acc = b1[o];
            #pragma unroll
            for (int i = 0; i < 10; i++) acc = fmaf(h0[i], W1[o * 10 + i], acc);
            h1[o] = fmaxf(acc, 0.f);
        }
        float l = b2[0];
        #pragma unroll
        for (int i = 0; i < 5; i++) l = fmaf(h1[i], W2[i], l);
        g_logits[pair][b] = l;
    }
}

__global__ void knrm_final(float* __restrict__ out)
{
    int b = blockIdx.x * blockDim.x + threadIdx.x;
    if (b < BATCH) {
        float d = g_logits[0][b] - g_logits[1][b];
        out[b] = 1.0f / (1.0f + expf(-d));
    }
}

extern "C" void kernel_launch(void* const* d_in, const int* in_sizes, int n_in,
                              void* d_out, int out_size)
{
    (void)in_sizes; (void)n_in; (void)out_size;
    const int*   q1  = (const int*)d_in[0];
    const int*   dd1 = (const int*)d_in[1];
    const int*   q2  = (const int*)d_in[2];
    const int*   dd2 = (const int*)d_in[3];
    const float* emb = (const float*)d_in[4];
    const float* W0  = (const float*)d_in[5];
    const float* b0  = (const float*)d_in[6];
    const float* W1  = (const float*)d_in[7];
    const float* b1  = (const float*)d_in[8];
    const float* W2  = (const float*)d_in[9];
    const float* b2  = (const float*)d_in[10];

    const int smem_bytes = (int)sizeof(SmemLayout);
    cudaFuncSetAttribute(knrm_main, cudaFuncAttributeMaxDynamicSharedMemorySize,
                         smem_bytes);

    dim3 grid(BATCH, 2);
    knrm_main<<<grid, THREADS, smem_bytes>>>(q1, dd1, q2, dd2, emb,
                                             W0, b0, W1, b1, W2, b2);
    knrm_final<<<(BATCH + 255) / 256, 256>>>((float*)d_out);
}